// round 15
// baseline (speedup 1.0000x reference)
#include <cuda_runtime.h>
#include <cuda_bf16.h>
#include <cuda_fp16.h>
#include <cstdint>
#include <float.h>

#define BATCHN 256
#define DDIM   512
#define HDIM   2048
#define SLOTSN 32768
#define CCAP   512
#define CDELTA 12.0f
#define PART_ELEMS (32*256*512)
#define K3_MK   (3*DDIM)      // 1536
#define K3_SL   (3*SLOTSN)    // 98304
#define K3_MLP1 (3*2*DDIM)    // 3072
#define K3_MLP2 (3*HDIM)      // 6144
#define MNP     (256*512)     // proj/R0 slice size

// ---------------- scratch ----------------
__device__ float g_K[BATCHN*DDIM];
__device__ float g_V[BATCHN*DDIM];
__device__ float g_G[BATCHN*BATCHN];
__device__ float g_base[(size_t)BATCHN*SLOTSN];
__device__ unsigned g_mU[BATCHN];                 // mapped-uint rowmax
__device__ float g_Z0[BATCHN];
__device__ float g_Zc[BATCHN];
__device__ float g_cand_val[BATCHN*CCAP];
__device__ int   g_cand_slot[BATCHN*CCAP];
__device__ int   g_cand_cnt[BATCHN];
__device__ int   g_slots[BATCHN];
__device__ int   g_nxt[BATCHN];
__device__ float g_Ccat[BATCHN*2*BATCHN];
__device__ float g_Vcat[2*BATCHN*DDIM];
__device__ float g_Part[PART_ELEMS];

// fp16 2-way-split (3-term) packed operands
__device__ unsigned short g_MKp3[(size_t)SLOTSN*K3_MK];
__device__ unsigned short g_KpA3[BATCHN*K3_MK];
__device__ unsigned short g_MVt3[(size_t)DDIM*K3_SL];
__device__ unsigned short g_Ep3[(size_t)BATCHN*K3_SL];
__device__ unsigned short g_Mgp3[BATCHN*K3_MLP1];
__device__ unsigned short g_W1p3[(size_t)HDIM*K3_MLP1];
__device__ unsigned short g_Hidp3[BATCHN*K3_MLP2];
__device__ unsigned short g_W2p3[(size_t)DDIM*K3_MLP2];

// ---------------- helpers ----------------
__device__ __forceinline__ unsigned short f2h(float x) {
    __half h = __float2half_rn(x);
    return *reinterpret_cast<unsigned short*>(&h);
}
__device__ __forceinline__ float h2f(unsigned short u) {
    __half h = *reinterpret_cast<__half*>(&u);
    return __half2float(h);
}
__device__ __forceinline__ unsigned mapf(float v) {
    unsigned u = __float_as_uint(v);
    return (u & 0x80000000u) ? ~u : (u | 0x80000000u);
}
__device__ __forceinline__ float unmapf(unsigned u) {
    unsigned x = (u & 0x80000000u) ? (u & 0x7FFFFFFFu) : ~u;
    return __uint_as_float(x);
}
__device__ __forceinline__ void cp16(unsigned d, const void* s) {
    asm volatile("cp.async.cg.shared.global [%0], [%1], 16;\n" :: "r"(d), "l"(s));
}
#define CP_COMMIT() asm volatile("cp.async.commit_group;\n")
#define MMA16816H(C0,C1,C2,C3,A0,A1,A2,A3,B0,B1) \
  asm volatile("mma.sync.aligned.m16n8k16.row.col.f32.f16.f16.f32 " \
    "{%0,%1,%2,%3},{%4,%5,%6,%7},{%8,%9},{%0,%1,%2,%3};\n" \
    : "+f"(C0),"+f"(C1),"+f"(C2),"+f"(C3) \
    : "r"(A0),"r"(A1),"r"(A2),"r"(A3),"r"(B0),"r"(B1))
__device__ __forceinline__ void ldsm_x4(unsigned &r0, unsigned &r1, unsigned &r2, unsigned &r3, unsigned addr) {
    asm volatile("ldmatrix.sync.aligned.m8n8.x4.shared.b16 {%0,%1,%2,%3}, [%4];"
        : "=r"(r0), "=r"(r1), "=r"(r2), "=r"(r3) : "r"(addr));
}
__device__ __forceinline__ void ldsm_x2(unsigned &r0, unsigned &r1, unsigned addr) {
    asm volatile("ldmatrix.sync.aligned.m8n8.x2.shared.b16 {%0,%1}, [%2];"
        : "=r"(r0), "=r"(r1) : "r"(addr));
}

// ---------------- fused invariant packing + mU init ----------------
#define PK_MK (SLOTSN*DDIM/256)          // 65536
#define PK_MV ((SLOTSN/32)*(DDIM/32))    // 16384
#define PK_W1 (HDIM*2*DDIM/256)          // 8192
#define PK_W2 (DDIM*HDIM/256)            // 4096
__global__ void pack_all_kernel(const float* __restrict__ MK, const float* __restrict__ MV,
                                const float* __restrict__ W1, const float* __restrict__ W2,
                                unsigned short* __restrict__ MKp3, unsigned short* __restrict__ MVt3,
                                unsigned short* __restrict__ W1p3, unsigned short* __restrict__ W2p3,
                                unsigned* __restrict__ mU)
{
    int b = blockIdx.x, tid = threadIdx.x;
    if (b < PK_MK) {                                 // MK pack, B-mode [h1|h2|h1], Kd=512
        int idx = b * 256 + tid;
        int r = idx >> 9, k = idx & 511;
        float x = MK[idx];
        unsigned short h1 = f2h(x);
        unsigned short h2 = f2h(x - h2f(h1));
        size_t ro = (size_t)r * K3_MK;
        MKp3[ro + k] = h1; MKp3[ro + 512 + k] = h2; MKp3[ro + 1024 + k] = h1;
        return;
    }
    b -= PK_MK;
    if (b < PK_MV) {                                 // MV transpose pack, B-mode
        __shared__ float tile[32][33];
        int bx = b & 1023, by = b >> 10;
        int r0 = bx * 32, c0 = by * 32;
        int tx = tid & 31, ty = tid >> 5;            // (32, 8)
        #pragma unroll
        for (int q = 0; q < 4; q++)
            tile[ty + 8*q][tx] = MV[(size_t)(r0 + ty + 8*q) * DDIM + c0 + tx];
        __syncthreads();
        #pragma unroll
        for (int q = 0; q < 4; q++) {
            int c = c0 + ty + 8*q;
            int r = r0 + tx;
            float x = tile[tx][ty + 8*q];
            unsigned short h1 = f2h(x);
            unsigned short h2 = f2h(x - h2f(h1));
            size_t ro = (size_t)c * K3_SL;
            MVt3[ro + r] = h1;
            MVt3[ro + (size_t)SLOTSN + r] = h2;
            MVt3[ro + 2*(size_t)SLOTSN + r] = h1;
        }
        return;
    }
    b -= PK_MV;
    if (b < PK_W1) {                                 // W1 pack, B-mode, Kd=1024
        int idx = b * 256 + tid;
        int r = idx >> 10, k = idx & 1023;
        float x = W1[idx];
        unsigned short h1 = f2h(x);
        unsigned short h2 = f2h(x - h2f(h1));
        size_t ro = (size_t)r * K3_MLP1;
        W1p3[ro + k] = h1; W1p3[ro + 1024 + k] = h2; W1p3[ro + 2048 + k] = h1;
        return;
    }
    b -= PK_W1;
    if (b < PK_W2) {                                 // W2 pack, B-mode, Kd=2048
        int idx = b * 256 + tid;
        int r = idx >> 11, k = idx & 2047;
        float x = W2[idx];
        unsigned short h1 = f2h(x);
        unsigned short h2 = f2h(x - h2f(h1));
        size_t ro = (size_t)r * K3_MLP2;
        W2p3[ro + k] = h1; W2p3[ro + 2048 + k] = h2; W2p3[ro + 4096 + k] = h1;
        return;
    }
    mU[tid] = 0;                                     // rowmax init (one block)
}

// ---------------- fp16 TN tensor-core GEMM (ldmatrix; optional fused rowmax) ----
__global__ __launch_bounds__(256, 2) void mma_tn_kernel(
    const unsigned short* __restrict__ A, const unsigned short* __restrict__ B,
    float* __restrict__ C, const float* __restrict__ bias,
    int M, int N, int Kd, int kChunk, int relu, unsigned* __restrict__ mU)
{
    __shared__ unsigned short As[2][128*40];
    __shared__ unsigned short Bs[2][128*40];
    __shared__ unsigned mrow[128];
    const int tid = threadIdx.x;
    const int wid = tid >> 5, lane = tid & 31;
    const int wm = wid >> 2, wn = wid & 3;
    const int g = lane >> 2, t = lane & 3;
    const int m0 = blockIdx.y * 128, n0 = blockIdx.x * 128;
    const int k0 = blockIdx.z * kChunk;
    const int nIter = kChunk >> 5;

    if (tid < 128) mrow[tid] = 0;

    const int lr = tid >> 2;
    const int lc = (tid & 3) << 3;
    const unsigned short* Ag = A + (size_t)(m0 + lr) * Kd + k0 + lc;
    const unsigned short* Bg = B + (size_t)(n0 + lr) * Kd + k0 + lc;
    const size_t rowStep = (size_t)64 * Kd;

    unsigned dstA[2], dstB[2];
    dstA[0] = (unsigned)__cvta_generic_to_shared(&As[0][lr*40 + lc]);
    dstA[1] = (unsigned)__cvta_generic_to_shared(&As[1][lr*40 + lc]);
    dstB[0] = (unsigned)__cvta_generic_to_shared(&Bs[0][lr*40 + lc]);
    dstB[1] = (unsigned)__cvta_generic_to_shared(&Bs[1][lr*40 + lc]);

    unsigned aAddr[2], bAddr[2];
    {
        int arow = wm*64 + (lane & 15);
        int acol = (lane >> 4) << 3;
        aAddr[0] = (unsigned)__cvta_generic_to_shared(&As[0][arow*40 + acol]);
        aAddr[1] = (unsigned)__cvta_generic_to_shared(&As[1][arow*40 + acol]);
        int brow = wn*32 + (lane & 7);
        int bcol = ((lane >> 3) & 1) << 3;
        bAddr[0] = (unsigned)__cvta_generic_to_shared(&Bs[0][brow*40 + bcol]);
        bAddr[1] = (unsigned)__cvta_generic_to_shared(&Bs[1][brow*40 + bcol]);
    }

    float acc[4][4][4];
    #pragma unroll
    for (int mi = 0; mi < 4; mi++)
        #pragma unroll
        for (int ni = 0; ni < 4; ni++)
            #pragma unroll
            for (int q = 0; q < 4; q++) acc[mi][ni][q] = 0.f;

    {
        cp16(dstA[0], Ag); cp16(dstA[0] + 5120, Ag + rowStep);
        cp16(dstB[0], Bg); cp16(dstB[0] + 5120, Bg + rowStep);
        CP_COMMIT();
    }

    for (int kk = 0; kk < nIter; kk++) {
        int cur = kk & 1;
        if (kk + 1 < nIter) {
            const unsigned short* ap = Ag + ((kk+1) << 5);
            const unsigned short* bp = Bg + ((kk+1) << 5);
            cp16(dstA[cur^1], ap); cp16(dstA[cur^1] + 5120, ap + rowStep);
            cp16(dstB[cur^1], bp); cp16(dstB[cur^1] + 5120, bp + rowStep);
            CP_COMMIT();
            asm volatile("cp.async.wait_group 1;\n");
        } else {
            asm volatile("cp.async.wait_group 0;\n");
        }
        __syncthreads();

        #pragma unroll
        for (int ks = 0; ks < 2; ks++) {
            unsigned a[4][4], b[4][2];
            #pragma unroll
            for (int mi = 0; mi < 4; mi++)
                ldsm_x4(a[mi][0], a[mi][1], a[mi][2], a[mi][3],
                        aAddr[cur] + (mi*16*40 + ks*16) * 2);
            #pragma unroll
            for (int ni = 0; ni < 4; ni++)
                ldsm_x2(b[ni][0], b[ni][1],
                        bAddr[cur] + (ni*8*40 + ks*16) * 2);
            #pragma unroll
            for (int mi = 0; mi < 4; mi++)
                #pragma unroll
                for (int ni = 0; ni < 4; ni++)
                    MMA16816H(acc[mi][ni][0], acc[mi][ni][1], acc[mi][ni][2], acc[mi][ni][3],
                              a[mi][0], a[mi][1], a[mi][2], a[mi][3], b[ni][0], b[ni][1]);
        }
        __syncthreads();
    }

    const bool direct = (gridDim.z == 1);
    float* Cz = direct ? C : C + (size_t)blockIdx.z * M * N;
    float rmax[4][2];
    #pragma unroll
    for (int mi = 0; mi < 4; mi++) { rmax[mi][0] = -FLT_MAX; rmax[mi][1] = -FLT_MAX; }

    #pragma unroll
    for (int mi = 0; mi < 4; mi++)
        #pragma unroll
        for (int ni = 0; ni < 4; ni++) {
            int row = m0 + wm*64 + mi*16 + g;
            int col = n0 + wn*32 + ni*8 + 2*t;
            float v0 = acc[mi][ni][0], v1 = acc[mi][ni][1];
            float v2 = acc[mi][ni][2], v3 = acc[mi][ni][3];
            if (direct) {
                if (bias) { float b0 = bias[col], b1 = bias[col+1]; v0 += b0; v1 += b1; v2 += b0; v3 += b1; }
                if (relu) { v0 = fmaxf(v0,0.f); v1 = fmaxf(v1,0.f); v2 = fmaxf(v2,0.f); v3 = fmaxf(v3,0.f); }
            }
            rmax[mi][0] = fmaxf(rmax[mi][0], fmaxf(v0, v1));
            rmax[mi][1] = fmaxf(rmax[mi][1], fmaxf(v2, v3));
            *(float2*)&Cz[(size_t)row * N + col]       = make_float2(v0, v1);
            *(float2*)&Cz[(size_t)(row + 8) * N + col] = make_float2(v2, v3);
        }

    if (mU) {
        #pragma unroll
        for (int mi = 0; mi < 4; mi++) {
            atomicMax(&mrow[wm*64 + mi*16 + g],     mapf(rmax[mi][0]));
            atomicMax(&mrow[wm*64 + mi*16 + g + 8], mapf(rmax[mi][1]));
        }
        __syncthreads();
        if (tid < 128) atomicMax(&mU[m0 + tid], mrow[tid]);
    }
}

// ---------------- fp32 SIMT GEMM (exact ops: proj, G, Rc) ----------------
template<bool BT>
__global__ __launch_bounds__(256, 2) void gemm_kernel(
    const float* __restrict__ A, const float* __restrict__ B, float* __restrict__ C,
    int M, int N, int Kd, int kChunk)
{
    __shared__ float As[8][128];
    __shared__ float Bs[8][128];
    const int tid = threadIdx.x;
    const int tx = tid & 15, ty = tid >> 4;
    const int bn = blockIdx.x, bm = blockIdx.y, bz = blockIdx.z;
    const int k0 = bz * kChunk;

    const int ar = tid >> 1, aq = (tid & 1) << 2;
    const float* Arow = A + (size_t)(bm*128 + ar)*Kd + aq;
    const float* Brow;
    if (BT) Brow = B + (size_t)(bn*128 + ar)*Kd + aq;
    else    Brow = B + (size_t)(k0 + (tid >> 5))*N + bn*128 + ((tid & 31) << 2);

    float acc[8][8];
    #pragma unroll
    for (int r = 0; r < 8; r++)
        #pragma unroll
        for (int c = 0; c < 8; c++) acc[r][c] = 0.f;

    for (int k = k0; k < k0 + kChunk; k += 8) {
        float4 av = *(const float4*)(Arow + k);
        As[aq+0][ar] = av.x; As[aq+1][ar] = av.y; As[aq+2][ar] = av.z; As[aq+3][ar] = av.w;
        if (BT) {
            float4 bv = *(const float4*)(Brow + k);
            Bs[aq+0][ar] = bv.x; Bs[aq+1][ar] = bv.y; Bs[aq+2][ar] = bv.z; Bs[aq+3][ar] = bv.w;
        } else {
            float4 bv = *(const float4*)Brow;
            *(float4*)&Bs[tid >> 5][(tid & 31) << 2] = bv;
            Brow += 8 * (size_t)N;
        }
        __syncthreads();
        #pragma unroll
        for (int kk = 0; kk < 8; kk++) {
            float a[8], b[8];
            *(float4*)&a[0] = *(const float4*)&As[kk][ty << 2];
            *(float4*)&a[4] = *(const float4*)&As[kk][64 + (ty << 2)];
            *(float4*)&b[0] = *(const float4*)&Bs[kk][tx << 2];
            *(float4*)&b[4] = *(const float4*)&Bs[kk][64 + (tx << 2)];
            #pragma unroll
            for (int r = 0; r < 8; r++)
                #pragma unroll
                for (int c = 0; c < 8; c++) acc[r][c] += a[r] * b[c];
        }
        __syncthreads();
    }

    float* Cout = C + (size_t)bz * M * N;
    const int mbase = bm*128, nbase = bn*128;
    #pragma unroll
    for (int rh = 0; rh < 2; rh++)
        #pragma unroll
        for (int rr = 0; rr < 4; rr++) {
            int r = rh*4 + rr;
            int m = mbase + rh*64 + (ty << 2) + rr;
            float* crow = Cout + (size_t)m * N + nbase;
            *(float4*)(crow + (tx << 2))      = make_float4(acc[r][0], acc[r][1], acc[r][2], acc[r][3]);
            *(float4*)(crow + 64 + (tx << 2)) = make_float4(acc[r][4], acc[r][5], acc[r][6], acc[r][7]);
        }
}

__global__ void reduce_kernel(const float* __restrict__ P, float* __restrict__ C,
                              const float* __restrict__ bias, int MN, int N, int split, int relu)
{
    int idx = blockIdx.x * 256 + threadIdx.x;
    if (idx >= MN) return;
    float s = 0.f;
    for (int z = 0; z < split; z++) s += P[(size_t)z * MN + idx];
    if (bias) s += bias[idx % N];
    if (relu) s = fmaxf(s, 0.f);
    C[idx] = s;
}

// K-proj reduce: sum 8 partials + bias -> g_K, and emit A-mode pack KpA3 (Kd=512)
__global__ void reduce_packK_kernel(const float* __restrict__ P, const float* __restrict__ bk,
                                    float* __restrict__ K, unsigned short* __restrict__ Y)
{
    int idx = blockIdx.x * 256 + threadIdx.x;       // 256*512
    float s = 0.f;
    for (int z = 0; z < 8; z++) s += P[(size_t)z * MNP + idx];
    s += bk[idx & 511];
    K[idx] = s;
    int r = idx >> 9, k = idx & 511;
    unsigned short h1 = f2h(s);
    unsigned short h2 = f2h(s - h2f(h1));
    size_t ro = (size_t)r * K3_MK;
    Y[ro + k] = h1; Y[ro + 512 + k] = h1; Y[ro + 1024 + k] = h2;
}

// MLP1 reduce: sum 8 partials + b1 + relu -> A-mode pack Hidp3 (Kd=2048)
__global__ void reduce_packH_kernel(const float* __restrict__ P, const float* __restrict__ b1,
                                    unsigned short* __restrict__ Y)
{
    int idx = blockIdx.x * 256 + threadIdx.x;       // 256*2048
    float s = 0.f;
    for (int z = 0; z < 8; z++) s += P[(size_t)z * (256*2048) + idx];
    s = fmaxf(s + b1[idx & 2047], 0.f);
    int r = idx >> 11, k = idx & 2047;
    unsigned short h1 = f2h(s);
    unsigned short h2 = f2h(s - h2f(h1));
    size_t ro = (size_t)r * K3_MLP2;
    Y[ro + k] = h1; Y[ro + 2048 + k] = h1; Y[ro + 4096 + k] = h2;
}

// Ep3 = fp16 3-term A-mode pack of exp(base - m); Z0 row sums; candidates
__global__ void e_kernel(const float* __restrict__ base, const unsigned* __restrict__ mU,
                         unsigned short* __restrict__ Ep, float* __restrict__ Z0,
                         float* __restrict__ cval, int* __restrict__ cslot, int* __restrict__ ccnt)
{
    int i = blockIdx.x, tid = threadIdx.x;
    __shared__ int cnt;
    if (tid == 0) cnt = 0;
    __syncthreads();
    float mi = unmapf(mU[i]), thr = mi - CDELTA, z = 0.f;
    const float* row = base + (size_t)i * SLOTSN;
    size_t ro = (size_t)i * K3_SL;
    for (int s = tid; s < SLOTSN; s += 256) {
        float b = row[s];
        float e = __expf(b - mi);
        unsigned short h1 = f2h(e);
        unsigned short h2 = f2h(e - h2f(h1));
        Ep[ro + s] = h1;
        Ep[ro + (size_t)SLOTSN + s] = h1;
        Ep[ro + 2*(size_t)SLOTSN + s] = h2;
        z += e;
        if (b >= thr) {
            int idx = atomicAdd(&cnt, 1);
            if (idx < CCAP) { cval[i*CCAP + idx] = b; cslot[i*CCAP + idx] = s; }
        }
    }
    for (int o = 16; o; o >>= 1) z += __shfl_down_sync(0xffffffffu, z, o);
    __shared__ float sh[8];
    if ((tid & 31) == 0) sh[tid >> 5] = z;
    __syncthreads();
    if (tid == 0) { float r = 0; for (int w = 0; w < 8; w++) r += sh[w]; Z0[i] = r; ccnt[i] = cnt; }
}

__device__ __forceinline__ unsigned long long mk_key(float v, int slot)
{
    unsigned u = __float_as_uint(v);
    u = (u & 0x80000000u) ? ~u : (u | 0x80000000u);
    return ((unsigned long long)u << 32) | (unsigned)(0xFFFFFFFFu - (unsigned)slot);
}

// sequential slot chain — single warp, register-prefetched
__global__ void seq_kernel(const float* __restrict__ G,
                           const float* __restrict__ cval, const int* __restrict__ cslot,
                           const int* __restrict__ ccnt, const float* __restrict__ base,
                           int* __restrict__ slots_out, int* __restrict__ nxt_out)
{
    extern __shared__ short mapw[];
    __shared__ int slots_s[256];
    __shared__ unsigned char alive[256];
    __shared__ short nxt[256];
    int lane = threadIdx.x;

    for (int s = lane * 8; s < SLOTSN; s += 256)
        *(int4*)&mapw[s] = make_int4(-1, -1, -1, -1);
    for (int j = lane; j < 256; j += 32) { alive[j] = 0; nxt[j] = 1000; }
    __syncwarp();

    float4 rg0 = *(const float4*)&G[lane * 8];
    float4 rg1 = *(const float4*)&G[lane * 8 + 4];
    int pcnt = ccnt[0];
    float pv[4]; int ps[4];
    #pragma unroll
    for (int q = 0; q < 4; q++) {
        pv[q] = cval[lane + 32*q];
        ps[q] = cslot[lane + 32*q];
    }

    for (int i = 0; i < 256; i++) {
        float gv[8] = {rg0.x, rg0.y, rg0.z, rg0.w, rg1.x, rg1.y, rg1.z, rg1.w};
        int cnt = pcnt;
        float cv[4]; int cs[4];
        #pragma unroll
        for (int q = 0; q < 4; q++) { cv[q] = pv[q]; cs[q] = ps[q]; }

        if (i + 1 < 256) {
            rg0 = *(const float4*)&G[(i+1)*256 + lane*8];
            rg1 = *(const float4*)&G[(i+1)*256 + lane*8 + 4];
            pcnt = ccnt[i+1];
            #pragma unroll
            for (int q = 0; q < 4; q++) {
                pv[q] = cval[(i+1)*CCAP + lane + 32*q];
                ps[q] = cslot[(i+1)*CCAP + lane + 32*q];
            }
        }

        unsigned long long best = 0ull;
        #pragma unroll
        for (int q = 0; q < 8; q++) {
            int j = lane*8 + q;
            if (j < i && alive[j]) {
                unsigned long long k = mk_key(gv[q], slots_s[j]);
                if (k > best) best = k;
            }
        }
        bool needfull = (cnt > CCAP);
        bool found = false;
        if (!needfull) {
            #pragma unroll
            for (int q = 0; q < 4; q++) {
                int c = lane + 32*q;
                if (c < cnt && mapw[cs[q]] < 0) {
                    found = true;
                    unsigned long long k = mk_key(cv[q], cs[q]);
                    if (k > best) best = k;
                }
            }
            for (int c = lane + 128; c < cnt; c += 32) {
                int s = cslot[i*CCAP + c];
                if (mapw[s] < 0) {
                    found = true;
                    unsigned long long k = mk_key(cval[i*CCAP + c], s);
                    if (k > best) best = k;
                }
            }
        }
        if (!__any_sync(0xffffffffu, found) || needfull) {
            const float* row = base + (size_t)i * SLOTSN;
            for (int s4 = lane*4; s4 < SLOTSN; s4 += 128) {
                float4 v = *(const float4*)&row[s4];
                float vv[4] = {v.x, v.y, v.z, v.w};
                #pragma unroll
                for (int q = 0; q < 4; q++)
                    if (mapw[s4+q] < 0) {
                        unsigned long long k = mk_key(vv[q], s4+q);
                        if (k > best) best = k;
                    }
            }
        }
        #pragma unroll
        for (int o = 16; o; o >>= 1) {
            unsigned long long k = __shfl_xor_sync(0xffffffffu, best, o);
            if (k > best) best = k;
        }
        int slot = (int)(0xFFFFFFFFu - (unsigned)(best & 0xFFFFFFFFull));
        if (lane == 0) {
            int old = mapw[slot];
            if (old >= 0) { alive[old] = 0; nxt[old] = (short)i; }
            mapw[slot] = (short)i;
            alive[i] = 1;
            slots_s[i] = slot;
        }
        __syncwarp();
    }
    for (int j = lane; j < 256; j += 32) { slots_out[j] = slots_s[j]; nxt_out[j] = nxt[j]; }
}

// fused cbuild (blocks 0..255) + vcat (blocks 256..767); 512 threads
__global__ void cbuild_vcat_kernel(const float* __restrict__ G, const unsigned* __restrict__ mU,
                                   const float* __restrict__ base, const int* __restrict__ slots,
                                   const int* __restrict__ nxt, float* __restrict__ Ccat,
                                   float* __restrict__ Zc,
                                   const float* __restrict__ V, const float* __restrict__ mv,
                                   float* __restrict__ Vcat)
{
    int bb = blockIdx.x, tid = threadIdx.x;
    if (bb < 256) {
        int i = bb, j = tid;
        float c1 = 0.f, c2 = 0.f;
        float m = unmapf(mU[i]);
        if (j < 256 && j < i && nxt[j] >= i) {
            c1 = __expf(G[i*256 + j] - m);
            c2 = __expf(base[(size_t)i * SLOTSN + slots[j]] - m);
        }
        if (j < 256) {
            Ccat[i*512 + j] = c1;
            Ccat[i*512 + 256 + j] = -c2;
        }
        float d = c1 - c2;
        for (int o = 16; o; o >>= 1) d += __shfl_down_sync(0xffffffffu, d, o);
        __shared__ float sh[16];
        if ((tid & 31) == 0) sh[tid >> 5] = d;
        __syncthreads();
        if (tid == 0) { float r = 0; for (int w = 0; w < 16; w++) r += sh[w]; Zc[i] = r; }
    } else {
        int j = bb - 256, d = tid;
        if (j < 256) Vcat[(size_t)j*512 + d] = V[j*512 + d];
        else         Vcat[(size_t)j*512 + d] = mv[(size_t)slots[j-256]*512 + d];
    }
}

// merged: reduce R0 (Part 0..15) + Rc (Part 16..23), divide by Z, pack Mgp3 directly
__global__ void merged_kernel(const float* __restrict__ S, const float* __restrict__ P,
                              const float* __restrict__ Z0, const float* __restrict__ Zc,
                              unsigned short* __restrict__ Mgp)
{
    int i = blockIdx.x, d = threadIdx.x;
    int idx = i*512 + d;
    float r0v = 0.f, rcv = 0.f;
    #pragma unroll
    for (int z = 0; z < 16; z++) r0v += P[(size_t)z * MNP + idx];
    #pragma unroll
    for (int z = 16; z < 24; z++) rcv += P[(size_t)z * MNP + idx];
    float readv = (r0v + rcv) / (Z0[i] + Zc[i]);
    float sv = S[idx];
    size_t ro = (size_t)i * K3_MLP1;
    unsigned short h1 = f2h(sv), h2 = f2h(sv - h2f(h1));
    Mgp[ro + d] = h1; Mgp[ro + 1024 + d] = h1; Mgp[ro + 2048 + d] = h2;
    h1 = f2h(readv); h2 = f2h(readv - h2f(h1));
    Mgp[ro + 512 + d] = h1; Mgp[ro + 1024 + 512 + d] = h1; Mgp[ro + 2048 + 512 + d] = h2;
}

extern "C" void kernel_launch(void* const* d_in, const int* in_sizes, int n_in,
                              void* d_out, int out_size)
{
    (void)in_sizes; (void)n_in; (void)out_size;
    const float* S  = (const float*)d_in[0];
    const float* MK = (const float*)d_in[1];
    const float* MV = (const float*)d_in[2];
    const float* Wk = (const float*)d_in[3];
    const float* bk = (const float*)d_in[4];
    const float* Wv = (const float*)d_in[5];
    const float* bv = (const float*)d_in[6];
    const float* W1 = (const float*)d_in[7];
    const float* b1 = (const float*)d_in[8];
    const float* W2 = (const float*)d_in[9];
    const float* b2 = (const float*)d_in[10];
    float* out = (float*)d_out;

    float *pK, *pV, *pG, *pBase, *pZ0, *pZc, *pCval, *pCcat, *pVcat, *pPart;
    unsigned *pmU;
    int *pCslot, *pCcnt, *pSlots, *pNxt;
    unsigned short *pMKp3, *pKpA3, *pMVt3, *pEp3, *pMgp3, *pW1p3, *pHidp3, *pW2p3;
    cudaGetSymbolAddress((void**)&pK, g_K);
    cudaGetSymbolAddress((void**)&pV, g_V);
    cudaGetSymbolAddress((void**)&pG, g_G);
    cudaGetSymbolAddress((void**)&pBase, g_base);
    cudaGetSymbolAddress((void**)&pmU, g_mU);
    cudaGetSymbolAddress((void**)&pZ0, g_Z0);
    cudaGetSymbolAddress((void**)&pZc, g_Zc);
    cudaGetSymbolAddress((void**)&pCval, g_cand_val);
    cudaGetSymbolAddress((void**)&pCslot, g_cand_slot);
    cudaGetSymbolAddress((void**)&pCcnt, g_cand_cnt);
    cudaGetSymbolAddress((void**)&pSlots, g_slots);
    cudaGetSymbolAddress((void**)&pNxt, g_nxt);
    cudaGetSymbolAddress((void**)&pCcat, g_Ccat);
    cudaGetSymbolAddress((void**)&pVcat, g_Vcat);
    cudaGetSymbolAddress((void**)&pPart, g_Part);
    cudaGetSymbolAddress((void**)&pMKp3, g_MKp3);
    cudaGetSymbolAddress((void**)&pKpA3, g_KpA3);
    cudaGetSymbolAddress((void**)&pMVt3, g_MVt3);
    cudaGetSymbolAddress((void**)&pEp3, g_Ep3);
    cudaGetSymbolAddress((void**)&pMgp3, g_Mgp3);
    cudaGetSymbolAddress((void**)&pW1p3, g_W1p3);
    cudaGetSymbolAddress((void**)&pHidp3, g_Hidp3);
    cudaGetSymbolAddress((void**)&pW2p3, g_W2p3);

    dim3 thr(256);

    // 1. all invariant packs + mU init
    pack_all_kernel<<<PK_MK + PK_MV + PK_W1 + PK_W2 + 1, thr>>>(
        MK, MV, W1, W2, pMKp3, pMVt3, pW1p3, pW2p3, pmU);

    // 2-3. projections: K -> Part slices 0..7, V -> slices 8..15
    gemm_kernel<true><<<dim3(4, 2, 8), thr>>>(S, Wk, pPart, 256, 512, 512, 64);
    gemm_kernel<true><<<dim3(4, 2, 8), thr>>>(S, Wv, pPart + (size_t)8*MNP, 256, 512, 512, 64);
    // 4-5. reduces (K reduce also packs KpA3)
    reduce_packK_kernel<<<512, 256>>>(pPart, bk, pK, pKpA3);
    reduce_kernel<<<512, 256>>>(pPart + (size_t)8*MNP, pV, bv, MNP, 512, 8, 0);

    // 6-7. Gram G = K@K^T (fp32 exact)
    gemm_kernel<true><<<dim3(2, 2, 16), thr>>>(pK, pK, pPart, 256, 256, 512, 32);
    reduce_kernel<<<256, 256>>>(pPart, pG, nullptr, 256*256, 256, 16, 0);

    // 8. base = K @ mem_keys^T (HMMA) with fused rowmax
    mma_tn_kernel<<<dim3(256, 2, 1), thr>>>(pKpA3, pMKp3, pBase, nullptr, 256, 32768, K3_MK, K3_MK, 0, pmU);
    // 9. E pack + Z0 + candidates
    e_kernel<<<256, 256>>>(pBase, pmU, pEp3, pZ0, pCval, pCslot, pCcnt);

    // 10. R0 = E @ mem_vals (HMMA, split-K 16 -> Part 0..15)
    mma_tn_kernel<<<dim3(4, 2, 16), thr>>>(pEp3, pMVt3, pPart, nullptr, 256, 512, K3_SL, K3_SL/16, 0, nullptr);

    // 11. sequential slot chain
    cudaFuncSetAttribute(seq_kernel, cudaFuncAttributeMaxDynamicSharedMemorySize, SLOTSN * 2);
    seq_kernel<<<1, 32, SLOTSN * 2>>>(pG, pCval, pCslot, pCcnt, pBase, pSlots, pNxt);

    // 12. cbuild + vcat fused
    cbuild_vcat_kernel<<<768, 512>>>(pG, pmU, pBase, pSlots, pNxt, pCcat, pZc, pV, MV, pVcat);
    // 13. Rc = Ccat @ Vcat -> Part slices 16..23
    gemm_kernel<false><<<dim3(4, 2, 8), thr>>>(pCcat, pVcat, pPart + (size_t)16*MNP, 256, 512, 512, 64);

    // 14. merged: reduce R0+Rc, divide, pack Mgp3
    merged_kernel<<<256, 512>>>(S, pPart, pZ0, pZc, pMgp3);

    // 15-18. MLP on HMMA
    mma_tn_kernel<<<dim3(16, 2, 8), thr>>>(pMgp3, pW1p3, pPart, nullptr, 256, 2048, K3_MLP1, K3_MLP1/8, 0, nullptr);
    reduce_packH_kernel<<<2048, 256>>>(pPart, b1, pHidp3);
    mma_tn_kernel<<<dim3(4, 2, 16), thr>>>(pHidp3, pW2p3, pPart, nullptr, 256, 512, K3_MLP2, K3_MLP2/16, 0, nullptr);
    reduce_kernel<<<512, 256>>>(pPart, out, b2, MNP, 512, 16, 0);
}

// round 16
// speedup vs baseline: 1.4596x; 1.4596x over previous
#include <cuda_runtime.h>
#include <cuda_bf16.h>
#include <cuda_fp16.h>
#include <cstdint>
#include <float.h>

#define BATCHN 256
#define DDIM   512
#define HDIM   2048
#define SLOTSN 32768
#define CCAP   512
#define CDELTA 12.0f
#define PART_ELEMS (32*256*512)
#define K3_MK   (3*DDIM)      // 1536
#define K3_SL   (3*SLOTSN)    // 98304
#define K3_MLP1 (3*2*DDIM)    // 3072
#define K3_MLP2 (3*HDIM)      // 6144
#define MNP     (256*512)

// ---------------- scratch ----------------
__device__ float g_K[BATCHN*DDIM];
__device__ float g_V[BATCHN*DDIM];
__device__ float g_G[BATCHN*BATCHN];
__device__ float g_base[(size_t)BATCHN*SLOTSN];
__device__ float g_m[BATCHN];
__device__ float g_Z0[BATCHN];
__device__ float g_Zc[BATCHN];
__device__ float g_cand_val[BATCHN*CCAP];
__device__ int   g_cand_slot[BATCHN*CCAP];
__device__ int   g_cand_cnt[BATCHN];
__device__ int   g_slots[BATCHN];
__device__ int   g_nxt[BATCHN];
__device__ float g_Ccat[BATCHN*2*BATCHN];
__device__ float g_Vcat[2*BATCHN*DDIM];
__device__ float g_Part[PART_ELEMS];

// fp16 2-way-split (3-term) packed operands
__device__ unsigned short g_MKp3[(size_t)SLOTSN*K3_MK];
__device__ unsigned short g_KpA3[BATCHN*K3_MK];
__device__ unsigned short g_MVt3[(size_t)DDIM*K3_SL];
__device__ unsigned short g_Ep3[(size_t)BATCHN*K3_SL];
__device__ unsigned short g_Mgp3[BATCHN*K3_MLP1];
__device__ unsigned short g_W1p3[(size_t)HDIM*K3_MLP1];
__device__ unsigned short g_Hidp3[BATCHN*K3_MLP2];
__device__ unsigned short g_W2p3[(size_t)DDIM*K3_MLP2];

// ---------------- helpers ----------------
__device__ __forceinline__ unsigned short f2h(float x) {
    __half h = __float2half_rn(x);
    return *reinterpret_cast<unsigned short*>(&h);
}
__device__ __forceinline__ float h2f(unsigned short u) {
    __half h = *reinterpret_cast<__half*>(&u);
    return __half2float(h);
}
__device__ __forceinline__ void cp16(unsigned d, const void* s) {
    asm volatile("cp.async.cg.shared.global [%0], [%1], 16;\n" :: "r"(d), "l"(s));
}
#define CP_COMMIT() asm volatile("cp.async.commit_group;\n")
#define MMA16816H(C0,C1,C2,C3,A0,A1,A2,A3,B0,B1) \
  asm volatile("mma.sync.aligned.m16n8k16.row.col.f32.f16.f16.f32 " \
    "{%0,%1,%2,%3},{%4,%5,%6,%7},{%8,%9},{%0,%1,%2,%3};\n" \
    : "+f"(C0),"+f"(C1),"+f"(C2),"+f"(C3) \
    : "r"(A0),"r"(A1),"r"(A2),"r"(A3),"r"(B0),"r"(B1))
__device__ __forceinline__ void ldsm_x4(unsigned &r0, unsigned &r1, unsigned &r2, unsigned &r3, unsigned addr) {
    asm volatile("ldmatrix.sync.aligned.m8n8.x4.shared.b16 {%0,%1,%2,%3}, [%4];"
        : "=r"(r0), "=r"(r1), "=r"(r2), "=r"(r3) : "r"(addr));
}
__device__ __forceinline__ void ldsm_x2(unsigned &r0, unsigned &r1, unsigned addr) {
    asm volatile("ldmatrix.sync.aligned.m8n8.x2.shared.b16 {%0,%1}, [%2];"
        : "=r"(r0), "=r"(r1) : "r"(addr));
}

// ---------------- fp16 3-term packing (R14 form: lean, per-operand) ----------
__global__ void pack_split3h_kernel(const float* __restrict__ X, unsigned short* __restrict__ Y,
                                    int total, int Kd, int bmode)
{
    int idx = blockIdx.x * 256 + threadIdx.x;
    if (idx >= total) return;
    int r = idx / Kd, k = idx - r * Kd;
    float x = X[idx];
    unsigned short h1 = f2h(x);
    unsigned short h2 = f2h(x - h2f(h1));
    size_t ro = (size_t)r * (3 * Kd);
    Y[ro + k] = h1;
    Y[ro + Kd + k] = bmode ? h2 : h1;
    Y[ro + 2*Kd + k] = bmode ? h1 : h2;
}

// MV [SLOTSN, DDIM] -> MVt3 [DDIM, 3*SLOTSN] fp16 B-mode [h1|h2|h1]
__global__ void transpose_pack3h_kernel(const float* __restrict__ X, unsigned short* __restrict__ Y)
{
    __shared__ float tile[32][33];
    int r0 = blockIdx.x * 32, c0 = blockIdx.y * 32;
    int tx = threadIdx.x, ty = threadIdx.y;     // (32, 8)
    #pragma unroll
    for (int q = 0; q < 4; q++)
        tile[ty + 8*q][tx] = X[(size_t)(r0 + ty + 8*q) * DDIM + c0 + tx];
    __syncthreads();
    #pragma unroll
    for (int q = 0; q < 4; q++) {
        int c = c0 + ty + 8*q;
        int r = r0 + tx;
        float x = tile[tx][ty + 8*q];
        unsigned short h1 = f2h(x);
        unsigned short h2 = f2h(x - h2f(h1));
        size_t ro = (size_t)c * K3_SL;
        Y[ro + r] = h1;
        Y[ro + (size_t)SLOTSN + r] = h2;
        Y[ro + 2*(size_t)SLOTSN + r] = h1;
    }
}

// ---------------- fp16 TN tensor-core GEMM (R14, untouched) ----------------
__global__ __launch_bounds__(256, 2) void mma_tn_kernel(
    const unsigned short* __restrict__ A, const unsigned short* __restrict__ B,
    float* __restrict__ C, const float* __restrict__ bias,
    int M, int N, int Kd, int kChunk, int relu)
{
    __shared__ unsigned short As[2][128*40];
    __shared__ unsigned short Bs[2][128*40];
    const int tid = threadIdx.x;
    const int wid = tid >> 5, lane = tid & 31;
    const int wm = wid >> 2, wn = wid & 3;
    const int g = lane >> 2, t = lane & 3;
    const int m0 = blockIdx.y * 128, n0 = blockIdx.x * 128;
    const int k0 = blockIdx.z * kChunk;
    const int nIter = kChunk >> 5;

    const int lr = tid >> 2;
    const int lc = (tid & 3) << 3;
    const unsigned short* Ag = A + (size_t)(m0 + lr) * Kd + k0 + lc;
    const unsigned short* Bg = B + (size_t)(n0 + lr) * Kd + k0 + lc;
    const size_t rowStep = (size_t)64 * Kd;

    unsigned dstA[2], dstB[2];
    dstA[0] = (unsigned)__cvta_generic_to_shared(&As[0][lr*40 + lc]);
    dstA[1] = (unsigned)__cvta_generic_to_shared(&As[1][lr*40 + lc]);
    dstB[0] = (unsigned)__cvta_generic_to_shared(&Bs[0][lr*40 + lc]);
    dstB[1] = (unsigned)__cvta_generic_to_shared(&Bs[1][lr*40 + lc]);

    unsigned aAddr[2], bAddr[2];
    {
        int arow = wm*64 + (lane & 15);
        int acol = (lane >> 4) << 3;
        aAddr[0] = (unsigned)__cvta_generic_to_shared(&As[0][arow*40 + acol]);
        aAddr[1] = (unsigned)__cvta_generic_to_shared(&As[1][arow*40 + acol]);
        int brow = wn*32 + (lane & 7);
        int bcol = ((lane >> 3) & 1) << 3;
        bAddr[0] = (unsigned)__cvta_generic_to_shared(&Bs[0][brow*40 + bcol]);
        bAddr[1] = (unsigned)__cvta_generic_to_shared(&Bs[1][brow*40 + bcol]);
    }

    float acc[4][4][4];
    #pragma unroll
    for (int mi = 0; mi < 4; mi++)
        #pragma unroll
        for (int ni = 0; ni < 4; ni++)
            #pragma unroll
            for (int q = 0; q < 4; q++) acc[mi][ni][q] = 0.f;

    {
        cp16(dstA[0], Ag); cp16(dstA[0] + 5120, Ag + rowStep);
        cp16(dstB[0], Bg); cp16(dstB[0] + 5120, Bg + rowStep);
        CP_COMMIT();
    }

    for (int kk = 0; kk < nIter; kk++) {
        int cur = kk & 1;
        if (kk + 1 < nIter) {
            const unsigned short* ap = Ag + ((kk+1) << 5);
            const unsigned short* bp = Bg + ((kk+1) << 5);
            cp16(dstA[cur^1], ap); cp16(dstA[cur^1] + 5120, ap + rowStep);
            cp16(dstB[cur^1], bp); cp16(dstB[cur^1] + 5120, bp + rowStep);
            CP_COMMIT();
            asm volatile("cp.async.wait_group 1;\n");
        } else {
            asm volatile("cp.async.wait_group 0;\n");
        }
        __syncthreads();

        #pragma unroll
        for (int ks = 0; ks < 2; ks++) {
            unsigned a[4][4], b[4][2];
            #pragma unroll
            for (int mi = 0; mi < 4; mi++)
                ldsm_x4(a[mi][0], a[mi][1], a[mi][2], a[mi][3],
                        aAddr[cur] + (mi*16*40 + ks*16) * 2);
            #pragma unroll
            for (int ni = 0; ni < 4; ni++)
                ldsm_x2(b[ni][0], b[ni][1],
                        bAddr[cur] + (ni*8*40 + ks*16) * 2);
            #pragma unroll
            for (int mi = 0; mi < 4; mi++)
                #pragma unroll
                for (int ni = 0; ni < 4; ni++)
                    MMA16816H(acc[mi][ni][0], acc[mi][ni][1], acc[mi][ni][2], acc[mi][ni][3],
                              a[mi][0], a[mi][1], a[mi][2], a[mi][3], b[ni][0], b[ni][1]);
        }
        __syncthreads();
    }

    const bool direct = (gridDim.z == 1);
    float* Cz = direct ? C : C + (size_t)blockIdx.z * M * N;
    #pragma unroll
    for (int mi = 0; mi < 4; mi++)
        #pragma unroll
        for (int ni = 0; ni < 4; ni++) {
            int row = m0 + wm*64 + mi*16 + g;
            int col = n0 + wn*32 + ni*8 + 2*t;
            float v0 = acc[mi][ni][0], v1 = acc[mi][ni][1];
            float v2 = acc[mi][ni][2], v3 = acc[mi][ni][3];
            if (direct) {
                if (bias) { float b0 = bias[col], b1 = bias[col+1]; v0 += b0; v1 += b1; v2 += b0; v3 += b1; }
                if (relu) { v0 = fmaxf(v0,0.f); v1 = fmaxf(v1,0.f); v2 = fmaxf(v2,0.f); v3 = fmaxf(v3,0.f); }
            }
            *(float2*)&Cz[(size_t)row * N + col]       = make_float2(v0, v1);
            *(float2*)&Cz[(size_t)(row + 8) * N + col] = make_float2(v2, v3);
        }
}

// ---------------- fp32 SIMT GEMM (exact: proj, G, Rc) ----------------
template<bool BT>
__global__ __launch_bounds__(256, 2) void gemm_kernel(
    const float* __restrict__ A, const float* __restrict__ B, float* __restrict__ C,
    int M, int N, int Kd, int kChunk)
{
    __shared__ float As[8][128];
    __shared__ float Bs[8][128];
    const int tid = threadIdx.x;
    const int tx = tid & 15, ty = tid >> 4;
    const int bn = blockIdx.x, bm = blockIdx.y, bz = blockIdx.z;
    const int k0 = bz * kChunk;

    const int ar = tid >> 1, aq = (tid & 1) << 2;
    const float* Arow = A + (size_t)(bm*128 + ar)*Kd + aq;
    const float* Brow;
    if (BT) Brow = B + (size_t)(bn*128 + ar)*Kd + aq;
    else    Brow = B + (size_t)(k0 + (tid >> 5))*N + bn*128 + ((tid & 31) << 2);

    float acc[8][8];
    #pragma unroll
    for (int r = 0; r < 8; r++)
        #pragma unroll
        for (int c = 0; c < 8; c++) acc[r][c] = 0.f;

    for (int k = k0; k < k0 + kChunk; k += 8) {
        float4 av = *(const float4*)(Arow + k);
        As[aq+0][ar] = av.x; As[aq+1][ar] = av.y; As[aq+2][ar] = av.z; As[aq+3][ar] = av.w;
        if (BT) {
            float4 bv = *(const float4*)(Brow + k);
            Bs[aq+0][ar] = bv.x; Bs[aq+1][ar] = bv.y; Bs[aq+2][ar] = bv.z; Bs[aq+3][ar] = bv.w;
        } else {
            float4 bv = *(const float4*)Brow;
            *(float4*)&Bs[tid >> 5][(tid & 31) << 2] = bv;
            Brow += 8 * (size_t)N;
        }
        __syncthreads();
        #pragma unroll
        for (int kk = 0; kk < 8; kk++) {
            float a[8], b[8];
            *(float4*)&a[0] = *(const float4*)&As[kk][ty << 2];
            *(float4*)&a[4] = *(const float4*)&As[kk][64 + (ty << 2)];
            *(float4*)&b[0] = *(const float4*)&Bs[kk][tx << 2];
            *(float4*)&b[4] = *(const float4*)&Bs[kk][64 + (tx << 2)];
            #pragma unroll
            for (int r = 0; r < 8; r++)
                #pragma unroll
                for (int c = 0; c < 8; c++) acc[r][c] += a[r] * b[c];
        }
        __syncthreads();
    }

    float* Cout = C + (size_t)bz * M * N;
    const int mbase = bm*128, nbase = bn*128;
    #pragma unroll
    for (int rh = 0; rh < 2; rh++)
        #pragma unroll
        for (int rr = 0; rr < 4; rr++) {
            int r = rh*4 + rr;
            int m = mbase + rh*64 + (ty << 2) + rr;
            float* crow = Cout + (size_t)m * N + nbase;
            *(float4*)(crow + (tx << 2))      = make_float4(acc[r][0], acc[r][1], acc[r][2], acc[r][3]);
            *(float4*)(crow + 64 + (tx << 2)) = make_float4(acc[r][4], acc[r][5], acc[r][6], acc[r][7]);
        }
}

__global__ void reduce_kernel(const float* __restrict__ P, float* __restrict__ C,
                              const float* __restrict__ bias, int MN, int N, int split, int relu)
{
    int idx = blockIdx.x * 256 + threadIdx.x;
    if (idx >= MN) return;
    float s = 0.f;
    for (int z = 0; z < split; z++) s += P[(size_t)z * MN + idx];
    if (bias) s += bias[idx % N];
    if (relu) s = fmaxf(s, 0.f);
    C[idx] = s;
}

// K-proj reduce + A-mode pack KpA3 (Kd=512)
__global__ void reduce_packK_kernel(const float* __restrict__ P, const float* __restrict__ bk,
                                    float* __restrict__ K, unsigned short* __restrict__ Y)
{
    int idx = blockIdx.x * 256 + threadIdx.x;
    float s = 0.f;
    for (int z = 0; z < 8; z++) s += P[(size_t)z * MNP + idx];
    s += bk[idx & 511];
    K[idx] = s;
    int r = idx >> 9, k = idx & 511;
    unsigned short h1 = f2h(s);
    unsigned short h2 = f2h(s - h2f(h1));
    size_t ro = (size_t)r * K3_MK;
    Y[ro + k] = h1; Y[ro + 512 + k] = h1; Y[ro + 1024 + k] = h2;
}

// MLP1 reduce + relu + A-mode pack Hidp3 (Kd=2048)
__global__ void reduce_packH_kernel(const float* __restrict__ P, const float* __restrict__ b1,
                                    unsigned short* __restrict__ Y)
{
    int idx = blockIdx.x * 256 + threadIdx.x;
    float s = 0.f;
    for (int z = 0; z < 8; z++) s += P[(size_t)z * (256*2048) + idx];
    s = fmaxf(s + b1[idx & 2047], 0.f);
    int r = idx >> 11, k = idx & 2047;
    unsigned short h1 = f2h(s);
    unsigned short h2 = f2h(s - h2f(h1));
    size_t ro = (size_t)r * K3_MLP2;
    Y[ro + k] = h1; Y[ro + 2048 + k] = h1; Y[ro + 4096 + k] = h2;
}

__global__ void rowmax_kernel(const float* __restrict__ base, float* __restrict__ m)
{
    int i = blockIdx.x, tid = threadIdx.x;
    const float* row = base + (size_t)i * SLOTSN;
    float mx = -FLT_MAX;
    for (int s = tid; s < SLOTSN; s += 256) mx = fmaxf(mx, row[s]);
    for (int o = 16; o; o >>= 1) mx = fmaxf(mx, __shfl_down_sync(0xffffffffu, mx, o));
    __shared__ float sh[8];
    if ((tid & 31) == 0) sh[tid >> 5] = mx;
    __syncthreads();
    if (tid == 0) { float r = sh[0]; for (int w = 1; w < 8; w++) r = fmaxf(r, sh[w]); m[i] = r; }
}

// Ep3 pack of exp(base - m); Z0 row sums; candidates
__global__ void e_kernel(const float* __restrict__ base, const float* __restrict__ m,
                         unsigned short* __restrict__ Ep, float* __restrict__ Z0,
                         float* __restrict__ cval, int* __restrict__ cslot, int* __restrict__ ccnt)
{
    int i = blockIdx.x, tid = threadIdx.x;
    __shared__ int cnt;
    if (tid == 0) cnt = 0;
    __syncthreads();
    float mi = m[i], thr = mi - CDELTA, z = 0.f;
    const float* row = base + (size_t)i * SLOTSN;
    size_t ro = (size_t)i * K3_SL;
    for (int s = tid; s < SLOTSN; s += 256) {
        float b = row[s];
        float e = __expf(b - mi);
        unsigned short h1 = f2h(e);
        unsigned short h2 = f2h(e - h2f(h1));
        Ep[ro + s] = h1;
        Ep[ro + (size_t)SLOTSN + s] = h1;
        Ep[ro + 2*(size_t)SLOTSN + s] = h2;
        z += e;
        if (b >= thr) {
            int idx = atomicAdd(&cnt, 1);
            if (idx < CCAP) { cval[i*CCAP + idx] = b; cslot[i*CCAP + idx] = s; }
        }
    }
    for (int o = 16; o; o >>= 1) z += __shfl_down_sync(0xffffffffu, z, o);
    __shared__ float sh[8];
    if ((tid & 31) == 0) sh[tid >> 5] = z;
    __syncthreads();
    if (tid == 0) { float r = 0; for (int w = 0; w < 8; w++) r += sh[w]; Z0[i] = r; ccnt[i] = cnt; }
}

__device__ __forceinline__ unsigned long long mk_key(float v, int slot)
{
    unsigned u = __float_as_uint(v);
    u = (u & 0x80000000u) ? ~u : (u | 0x80000000u);
    return ((unsigned long long)u << 32) | (unsigned)(0xFFFFFFFFu - (unsigned)slot);
}

// sequential slot chain — single warp, register-prefetched
__global__ void seq_kernel(const float* __restrict__ G,
                           const float* __restrict__ cval, const int* __restrict__ cslot,
                           const int* __restrict__ ccnt, const float* __restrict__ base,
                           int* __restrict__ slots_out, int* __restrict__ nxt_out)
{
    extern __shared__ short mapw[];
    __shared__ int slots_s[256];
    __shared__ unsigned char alive[256];
    __shared__ short nxt[256];
    int lane = threadIdx.x;

    for (int s = lane * 8; s < SLOTSN; s += 256)
        *(int4*)&mapw[s] = make_int4(-1, -1, -1, -1);
    for (int j = lane; j < 256; j += 32) { alive[j] = 0; nxt[j] = 1000; }
    __syncwarp();

    float4 rg0 = *(const float4*)&G[lane * 8];
    float4 rg1 = *(const float4*)&G[lane * 8 + 4];
    int pcnt = ccnt[0];
    float pv[4]; int ps[4];
    #pragma unroll
    for (int q = 0; q < 4; q++) {
        pv[q] = cval[lane + 32*q];
        ps[q] = cslot[lane + 32*q];
    }

    for (int i = 0; i < 256; i++) {
        float gv[8] = {rg0.x, rg0.y, rg0.z, rg0.w, rg1.x, rg1.y, rg1.z, rg1.w};
        int cnt = pcnt;
        float cv[4]; int cs[4];
        #pragma unroll
        for (int q = 0; q < 4; q++) { cv[q] = pv[q]; cs[q] = ps[q]; }

        if (i + 1 < 256) {
            rg0 = *(const float4*)&G[(i+1)*256 + lane*8];
            rg1 = *(const float4*)&G[(i+1)*256 + lane*8 + 4];
            pcnt = ccnt[i+1];
            #pragma unroll
            for (int q = 0; q < 4; q++) {
                pv[q] = cval[(i+1)*CCAP + lane + 32*q];
                ps[q] = cslot[(i+1)*CCAP + lane + 32*q];
            }
        }

        unsigned long long best = 0ull;
        #pragma unroll
        for (int q = 0; q < 8; q++) {
            int j = lane*8 + q;
            if (j < i && alive[j]) {
                unsigned long long k = mk_key(gv[q], slots_s[j]);
                if (k > best) best = k;
            }
        }
        bool needfull = (cnt > CCAP);
        bool found = false;
        if (!needfull) {
            #pragma unroll
            for (int q = 0; q < 4; q++) {
                int c = lane + 32*q;
                if (c < cnt && mapw[cs[q]] < 0) {
                    found = true;
                    unsigned long long k = mk_key(cv[q], cs[q]);
                    if (k > best) best = k;
                }
            }
            for (int c = lane + 128; c < cnt; c += 32) {
                int s = cslot[i*CCAP + c];
                if (mapw[s] < 0) {
                    found = true;
                    unsigned long long k = mk_key(cval[i*CCAP + c], s);
                    if (k > best) best = k;
                }
            }
        }
        if (!__any_sync(0xffffffffu, found) || needfull) {
            const float* row = base + (size_t)i * SLOTSN;
            for (int s4 = lane*4; s4 < SLOTSN; s4 += 128) {
                float4 v = *(const float4*)&row[s4];
                float vv[4] = {v.x, v.y, v.z, v.w};
                #pragma unroll
                for (int q = 0; q < 4; q++)
                    if (mapw[s4+q] < 0) {
                        unsigned long long k = mk_key(vv[q], s4+q);
                        if (k > best) best = k;
                    }
            }
        }
        #pragma unroll
        for (int o = 16; o; o >>= 1) {
            unsigned long long k = __shfl_xor_sync(0xffffffffu, best, o);
            if (k > best) best = k;
        }
        int slot = (int)(0xFFFFFFFFu - (unsigned)(best & 0xFFFFFFFFull));
        if (lane == 0) {
            int old = mapw[slot];
            if (old >= 0) { alive[old] = 0; nxt[old] = (short)i; }
            mapw[slot] = (short)i;
            alive[i] = 1;
            slots_s[i] = slot;
        }
        __syncwarp();
    }
    for (int j = lane; j < 256; j += 32) { slots_out[j] = slots_s[j]; nxt_out[j] = nxt[j]; }
}

// fused cbuild (blocks 0..255) + vcat (blocks 256..767); 512 threads
__global__ void cbuild_vcat_kernel(const float* __restrict__ G, const float* __restrict__ m,
                                   const float* __restrict__ base, const int* __restrict__ slots,
                                   const int* __restrict__ nxt, float* __restrict__ Ccat,
                                   float* __restrict__ Zc,
                                   const float* __restrict__ V, const float* __restrict__ mv,
                                   float* __restrict__ Vcat)
{
    int bb = blockIdx.x, tid = threadIdx.x;
    if (bb < 256) {
        int i = bb, j = tid;
        float c1 = 0.f, c2 = 0.f;
        float mi = m[i];
        if (j < 256 && j < i && nxt[j] >= i) {
            c1 = __expf(G[i*256 + j] - mi);
            c2 = __expf(base[(size_t)i * SLOTSN + slots[j]] - mi);
        }
        if (j < 256) {
            Ccat[i*512 + j] = c1;
            Ccat[i*512 + 256 + j] = -c2;
        }
        float d = c1 - c2;
        for (int o = 16; o; o >>= 1) d += __shfl_down_sync(0xffffffffu, d, o);
        __shared__ float sh[16];
        if ((tid & 31) == 0) sh[tid >> 5] = d;
        __syncthreads();
        if (tid == 0) { float r = 0; for (int w = 0; w < 16; w++) r += sh[w]; Zc[i] = r; }
    } else {
        int j = bb - 256, d = tid;
        if (j < 256) Vcat[(size_t)j*512 + d] = V[j*512 + d];
        else         Vcat[(size_t)j*512 + d] = mv[(size_t)slots[j-256]*512 + d];
    }
}

// merged: reduce R0 (Part 0..15) + Rc (Part 16..23), divide, pack Mgp3
__global__ void merged_kernel(const float* __restrict__ S, const float* __restrict__ P,
                              const float* __restrict__ Z0, const float* __restrict__ Zc,
                              unsigned short* __restrict__ Mgp)
{
    int i = blockIdx.x, d = threadIdx.x;
    int idx = i*512 + d;
    float r0v = 0.f, rcv = 0.f;
    #pragma unroll
    for (int z = 0; z < 16; z++) r0v += P[(size_t)z * MNP + idx];
    #pragma unroll
    for (int z = 16; z < 24; z++) rcv += P[(size_t)z * MNP + idx];
    float readv = (r0v + rcv) / (Z0[i] + Zc[i]);
    float sv = S[idx];
    size_t ro = (size_t)i * K3_MLP1;
    unsigned short h1 = f2h(sv), h2 = f2h(sv - h2f(h1));
    Mgp[ro + d] = h1; Mgp[ro + 1024 + d] = h1; Mgp[ro + 2048 + d] = h2;
    h1 = f2h(readv); h2 = f2h(readv - h2f(h1));
    Mgp[ro + 512 + d] = h1; Mgp[ro + 1024 + 512 + d] = h1; Mgp[ro + 2048 + 512 + d] = h2;
}

extern "C" void kernel_launch(void* const* d_in, const int* in_sizes, int n_in,
                              void* d_out, int out_size)
{
    (void)in_sizes; (void)n_in; (void)out_size;
    const float* S  = (const float*)d_in[0];
    const float* MK = (const float*)d_in[1];
    const float* MV = (const float*)d_in[2];
    const float* Wk = (const float*)d_in[3];
    const float* bk = (const float*)d_in[4];
    const float* Wv = (const float*)d_in[5];
    const float* bv = (const float*)d_in[6];
    const float* W1 = (const float*)d_in[7];
    const float* b1 = (const float*)d_in[8];
    const float* W2 = (const float*)d_in[9];
    const float* b2 = (const float*)d_in[10];
    float* out = (float*)d_out;

    float *pK, *pV, *pG, *pBase, *pm, *pZ0, *pZc, *pCval, *pCcat, *pVcat, *pPart;
    int *pCslot, *pCcnt, *pSlots, *pNxt;
    unsigned short *pMKp3, *pKpA3, *pMVt3, *pEp3, *pMgp3, *pW1p3, *pHidp3, *pW2p3;
    cudaGetSymbolAddress((void**)&pK, g_K);
    cudaGetSymbolAddress((void**)&pV, g_V);
    cudaGetSymbolAddress((void**)&pG, g_G);
    cudaGetSymbolAddress((void**)&pBase, g_base);
    cudaGetSymbolAddress((void**)&pm, g_m);
    cudaGetSymbolAddress((void**)&pZ0, g_Z0);
    cudaGetSymbolAddress((void**)&pZc, g_Zc);
    cudaGetSymbolAddress((void**)&pCval, g_cand_val);
    cudaGetSymbolAddress((void**)&pCslot, g_cand_slot);
    cudaGetSymbolAddress((void**)&pCcnt, g_cand_cnt);
    cudaGetSymbolAddress((void**)&pSlots, g_slots);
    cudaGetSymbolAddress((void**)&pNxt, g_nxt);
    cudaGetSymbolAddress((void**)&pCcat, g_Ccat);
    cudaGetSymbolAddress((void**)&pVcat, g_Vcat);
    cudaGetSymbolAddress((void**)&pPart, g_Part);
    cudaGetSymbolAddress((void**)&pMKp3, g_MKp3);
    cudaGetSymbolAddress((void**)&pKpA3, g_KpA3);
    cudaGetSymbolAddress((void**)&pMVt3, g_MVt3);
    cudaGetSymbolAddress((void**)&pEp3, g_Ep3);
    cudaGetSymbolAddress((void**)&pMgp3, g_Mgp3);
    cudaGetSymbolAddress((void**)&pW1p3, g_W1p3);
    cudaGetSymbolAddress((void**)&pHidp3, g_Hidp3);
    cudaGetSymbolAddress((void**)&pW2p3, g_W2p3);

    dim3 thr(256);

    // invariant packs (lean R14 kernels)
    pack_split3h_kernel<<<(SLOTSN*DDIM + 255)/256, thr>>>(MK, pMKp3, SLOTSN*DDIM, DDIM, 1);
    transpose_pack3h_kernel<<<dim3(SLOTSN/32, DDIM/32), dim3(32, 8)>>>(MV, pMVt3);
    pack_split3h_kernel<<<(HDIM*2*DDIM + 255)/256, thr>>>(W1, pW1p3, HDIM*2*DDIM, 2*DDIM, 1);
    pack_split3h_kernel<<<(DDIM*HDIM + 255)/256, thr>>>(W2, pW2p3, DDIM*HDIM, HDIM, 1);

    // projections: K -> Part 0..7, V -> Part 8..15; fused reduce+pack for K
    gemm_kernel<true><<<dim3(4, 2, 8), thr>>>(S, Wk, pPart, 256, 512, 512, 64);
    gemm_kernel<true><<<dim3(4, 2, 8), thr>>>(S, Wv, pPart + (size_t)8*MNP, 256, 512, 512, 64);
    reduce_packK_kernel<<<512, 256>>>(pPart, bk, pK, pKpA3);
    reduce_kernel<<<512, 256>>>(pPart + (size_t)8*MNP, pV, bv, MNP, 512, 8, 0);

    // Gram G = K@K^T (fp32 exact)
    gemm_kernel<true><<<dim3(2, 2, 16), thr>>>(pK, pK, pPart, 256, 256, 512, 32);
    reduce_kernel<<<256, 256>>>(pPart, pG, nullptr, 256*256, 256, 16, 0);

    // base = K @ mem_keys^T (HMMA)
    mma_tn_kernel<<<dim3(256, 2, 1), thr>>>(pKpA3, pMKp3, pBase, nullptr, 256, 32768, K3_MK, K3_MK, 0);
    rowmax_kernel<<<256, 256>>>(pBase, pm);
    e_kernel<<<256, 256>>>(pBase, pm, pEp3, pZ0, pCval, pCslot, pCcnt);

    // R0 = E @ mem_vals (HMMA, split-K 16 -> Part 0..15)
    mma_tn_kernel<<<dim3(4, 2, 16), thr>>>(pEp3, pMVt3, pPart, nullptr, 256, 512, K3_SL, K3_SL/16, 0);

    // sequential slot chain
    cudaFuncSetAttribute(seq_kernel, cudaFuncAttributeMaxDynamicSharedMemorySize, SLOTSN * 2);
    seq_kernel<<<1, 32, SLOTSN * 2>>>(pG, pCval, pCslot, pCcnt, pBase, pSlots, pNxt);

    // cbuild + vcat fused; Rc -> Part 16..23
    cbuild_vcat_kernel<<<768, 512>>>(pG, pm, pBase, pSlots, pNxt, pCcat, pZc, pV, MV, pVcat);
    gemm_kernel<false><<<dim3(4, 2, 8), thr>>>(pCcat, pVcat, pPart + (size_t)16*MNP, 256, 512, 512, 64);

    // merged: reduce R0+Rc, divide, pack Mgp3
    merged_kernel<<<256, 512>>>(S, pPart, pZ0, pZc, pMgp3);

    // MLP on HMMA; MLP1 reduce fused with Hid pack
    mma_tn_kernel<<<dim3(16, 2, 8), thr>>>(pMgp3, pW1p3, pPart, nullptr, 256, 2048, K3_MLP1, K3_MLP1/8, 0);
    reduce_packH_kernel<<<2048, 256>>>(pPart, b1, pHidp3);
    mma_tn_kernel<<<dim3(4, 2, 16), thr>>>(pHidp3, pW2p3, pPart, nullptr, 256, 512, K3_MLP2, K3_MLP2/16, 0);
    reduce_kernel<<<512, 256>>>(pPart, out, b2, MNP, 512, 16, 0);
}